// round 16
// baseline (speedup 1.0000x reference)
#include <cuda_runtime.h>

// RelationCrossing — feats (R=8, N, K=8, d=64) fp32, rel_attn (8,64) fp32.
// scores[r,n,k] = leaky_relu(dot(feats[r,n,k,:], rel_attn[k,:]), 0.2)
// attn = softmax over r; out[n,k,:] = sum_r attn[r,n,k] * feats[r,n,k,:]
//
// Converged R11 structure (254.0us, DRAM 92.0%, traffic at the 1.843 GB
// floor) + the last untested lever: PER-CTA RELATION ROTATION. All CTAs
// previously issued loads r=0..7 in the same order, so the chip's concurrent
// load population clustered on one ~200MB relation slab at a time (correlated
// DRAM row pressure). Rotating each CTA's start relation by blockIdx&7
// spreads simultaneous loads across all 8 slabs -> more DRAM banks/rows
// active concurrently, fewer activate/precharge stalls. Correctness-safe:
// softmax over r is permutation-invariant and s/f stay index-paired.

#define R 8
#define NEG_SLOPE 0.2f

__global__ __launch_bounds__(256) void relation_crossing_kernel(
    const float4* __restrict__ feats,   // R * N * 128 float4s
    const float4* __restrict__ rel,     // 128 float4s (8 heads * 16 quarters)
    float4* __restrict__ out,           // N * 128 float4s
    int total4,                         // N * 128
    long long rel_stride4)              // N * 128 (float4 stride between relations)
{
    int idx = blockIdx.x * blockDim.x + threadIdx.x;
    if (idx >= total4) return;

    // idx = n*128 + k*16 + q  (k = head, q = d-quarter). rel index = k*16+q.
    float4 ra = rel[idx & 127];

    // Per-CTA rotation of the relation visit order (block-uniform).
    int rot = blockIdx.x & (R - 1);

    // Front-batched loads: 8 independent LDG.128 (MLP=8), dot partials folded
    // in as each lands. f[]/s[] are indexed by the rotated relation rr so the
    // softmax weight w[rr] pairs with the matching f[rr].
    float4 f[R];
    float s[R];
#pragma unroll
    for (int r = 0; r < R; r++) {
        int rr = (r + rot) & (R - 1);
        f[rr] = feats[(long long)rr * rel_stride4 + idx];
        s[rr] = f[rr].x * ra.x + f[rr].y * ra.y + f[rr].z * ra.z + f[rr].w * ra.w;
    }

    // Reduce dot products across the 16-thread group covering this head.
    // Groups of 16 are warp-aligned, so xor offsets 8,4,2,1 stay in-group.
#pragma unroll
    for (int off = 8; off >= 1; off >>= 1) {
#pragma unroll
        for (int r = 0; r < R; r++)
            s[r] += __shfl_xor_sync(0xffffffffu, s[r], off);
    }

    // leaky_relu + softmax over relations (order-invariant reductions).
    float m = -3.4e38f;
#pragma unroll
    for (int r = 0; r < R; r++) {
        s[r] = (s[r] > 0.0f) ? s[r] : NEG_SLOPE * s[r];
        m = fmaxf(m, s[r]);
    }
    float sum = 0.0f;
#pragma unroll
    for (int r = 0; r < R; r++) {
        s[r] = __expf(s[r] - m);
        sum += s[r];
    }
    float inv = __frcp_rn(sum);

    float4 o = make_float4(0.f, 0.f, 0.f, 0.f);
#pragma unroll
    for (int r = 0; r < R; r++) {
        float w = s[r] * inv;
        o.x = fmaf(w, f[r].x, o.x);
        o.y = fmaf(w, f[r].y, o.y);
        o.z = fmaf(w, f[r].z, o.z);
        o.w = fmaf(w, f[r].w, o.w);
    }
    __stwt(&out[idx], o);   // STG.WT — write-through, no dirty-L2 eviction bursts
}

extern "C" void kernel_launch(void* const* d_in, const int* in_sizes, int n_in,
                              void* d_out, int out_size)
{
    const float4* feats = (const float4*)d_in[0];  // (8, N, 512) fp32
    const float4* rel   = (const float4*)d_in[1];  // (8, 64) fp32
    float4* out = (float4*)d_out;                  // (N, 512) fp32

    long long elems_per_rel = (long long)in_sizes[0] / R;   // N*512 floats
    int total4 = (int)(elems_per_rel / 4);                  // N*128 float4
    long long rel_stride4 = total4;

    int threads = 256;
    int blocks = (total4 + threads - 1) / threads;
    relation_crossing_kernel<<<blocks, threads>>>(feats, rel, out, total4, rel_stride4);
}

// round 17
// speedup vs baseline: 2.1843x; 2.1843x over previous
#include <cuda_runtime.h>

// RelationCrossing — FINAL (converged optimum; 254.0-255.3us across four
// reproductions, DRAM 91.4-92.0% = 7.25-7.29 TB/s).
// feats (R=8, N, K=8, d=64) fp32, rel_attn (8,64) fp32.
// scores[r,n,k] = leaky_relu(dot(feats[r,n,k,:], rel_attn[k,:]), 0.2)
// attn = softmax over r; out[n,k,:] = sum_r attn[r,n,k] * feats[r,n,k,:]
//
// Single-pass, register-resident: each thread owns a float4 (4 d-values) of
// one (n,k); 16 warp-aligned threads cover a head; dot reduced via 4-level
// xor-shuffle butterfly; softmax redundant per lane (compute ~20% util, free);
// weighted sum from registers; __stwt (STG.WT) store — write-through keeps
// LTS dirty-eviction bursts out of the 8-stream read interleave.
//
// Traffic at the theoretical floor (1.638 GB read + 0.205 GB write).
// 16-round sweep ruled out: occupancy (44-62% flat on DRAM%), block size,
// cp.async SMEM staging (-14%), float2 granularity (-7%), persistent grid +
// SW pipeline (-24%), two-pass L2 re-read (-3%), streaming read hints,
// split-batch reduction, launch-bounds capping, per-CTA relation rotation
// (dynamic indexing -> select chains, -118%). Residual ~8% is HBM read/write
// turnaround on the 8:1 mix — not kernel-addressable.
// (redux.sync.add.f32 does not exist on sm_103.)

#define R 8
#define NEG_SLOPE 0.2f

__global__ __launch_bounds__(256) void relation_crossing_kernel(
    const float4* __restrict__ feats,   // R * N * 128 float4s
    const float4* __restrict__ rel,     // 128 float4s (8 heads * 16 quarters)
    float4* __restrict__ out,           // N * 128 float4s
    int total4,                         // N * 128
    long long rel_stride4)              // N * 128 (float4 stride between relations)
{
    int idx = blockIdx.x * blockDim.x + threadIdx.x;
    if (idx >= total4) return;

    // idx = n*128 + k*16 + q  (k = head, q = d-quarter). rel index = k*16+q.
    float4 ra = rel[idx & 127];

    // Front-batched loads: 8 independent LDG.128 (MLP=8), dot partials folded
    // in as each lands. Static indexing only — keeps f[]/s[] in registers.
    float4 f[R];
    float s[R];
#pragma unroll
    for (int r = 0; r < R; r++) {
        f[r] = feats[(long long)r * rel_stride4 + idx];
        s[r] = f[r].x * ra.x + f[r].y * ra.y + f[r].z * ra.z + f[r].w * ra.w;
    }

    // Reduce dot products across the 16-thread group covering this head.
    // Groups of 16 are warp-aligned, so xor offsets 8,4,2,1 stay in-group;
    // 8 independent values per level -> serial chain is 4 SHFL latencies.
#pragma unroll
    for (int off = 8; off >= 1; off >>= 1) {
#pragma unroll
        for (int r = 0; r < R; r++)
            s[r] += __shfl_xor_sync(0xffffffffu, s[r], off);
    }

    // leaky_relu + softmax over relations (identical across the 16-lane group).
    float m = -3.4e38f;
#pragma unroll
    for (int r = 0; r < R; r++) {
        s[r] = (s[r] > 0.0f) ? s[r] : NEG_SLOPE * s[r];
        m = fmaxf(m, s[r]);
    }
    float sum = 0.0f;
#pragma unroll
    for (int r = 0; r < R; r++) {
        s[r] = __expf(s[r] - m);
        sum += s[r];
    }
    float inv = __frcp_rn(sum);

    float4 o = make_float4(0.f, 0.f, 0.f, 0.f);
#pragma unroll
    for (int r = 0; r < R; r++) {
        float w = s[r] * inv;
        o.x = fmaf(w, f[r].x, o.x);
        o.y = fmaf(w, f[r].y, o.y);
        o.z = fmaf(w, f[r].z, o.z);
        o.w = fmaf(w, f[r].w, o.w);
    }
    __stwt(&out[idx], o);   // STG.WT — write-through, no dirty-L2 eviction bursts
}

extern "C" void kernel_launch(void* const* d_in, const int* in_sizes, int n_in,
                              void* d_out, int out_size)
{
    const float4* feats = (const float4*)d_in[0];  // (8, N, 512) fp32
    const float4* rel   = (const float4*)d_in[1];  // (8, 64) fp32
    float4* out = (float4*)d_out;                  // (N, 512) fp32

    long long elems_per_rel = (long long)in_sizes[0] / R;   // N*512 floats
    int total4 = (int)(elems_per_rel / 4);                  // N*128 float4
    long long rel_stride4 = total4;

    int threads = 256;
    int blocks = (total4 + threads - 1) / threads;
    relation_crossing_kernel<<<blocks, threads>>>(feats, rel, out, total4, rel_stride4);
}